// round 11
// baseline (speedup 1.0000x reference)
#include <cuda_runtime.h>
#include <cuda_bf16.h>

// ---------------------------------------------------------------------------
// TensorCircuit forward, linear domain, bf16 activation storage.
//   input:  lin0[i,b] = softmax(in_logits[i])[x[b, i/32]]         (bf16)
//   prod l: em[e,b]   = prev[p0,b]*prev[p1,b] (/ m2^2 at layer 3) (bf16)
//   sum  l: s[s,b]    = sum_c softmax(w[s])[c] * em[cid,b]        (bf16, fp32 acc)
//   renorm: single per-batch-column max m2 after s2
//   layer4 prod+sum collapsed into k_root (only 32 of 1024 elements used).
//   root   = log( sum_c w4_c * s3[p0_c]*s3[p1_c] ) + 4*log m2     (fp32)
// ---------------------------------------------------------------------------

#define BATCH 1024
#define NV    256
#define NK    64
#define NM    32
#define NN0   8192

// bf16 arena (element offsets). All offsets are multiples of 1024 -> 16B aligned.
#define LIN0  0u
#define EMO   (8192u * 1024u)
#define S1O   (EMO + 8192u * 1024u)
#define S2O   (S1O + 4096u * 1024u)
#define S3O   (S2O + 2048u * 1024u)
#define BF_SZ (S3O + 1024u * 1024u)

__device__ __nv_bfloat16 g_bf[BF_SZ];
__device__ float g_m[BATCH];        // per-column renorm max m2 (fp32)

// --- bf16 bit-trick helpers -------------------------------------------------
__device__ __forceinline__ float lo_bf(unsigned u) { return __uint_as_float(u << 16); }
__device__ __forceinline__ float hi_bf(unsigned u) { return __uint_as_float(u & 0xffff0000u); }
__device__ __forceinline__ unsigned pack_bf2(float lo, float hi) {
    unsigned r;
    asm("cvt.rn.bf16x2.f32 %0, %1, %2;" : "=r"(r) : "f"(hi), "f"(lo));
    return r;
}

// Fused input layer: per-variable block computes the 32-row softmax tile in
// smem (transposed, padded), then each thread gathers for a COLUMN PAIR and
// writes packed bf16x2 -> full 128B store wavefronts. Blocks 0..3 zero g_m.
__global__ void __launch_bounds__(256) k_inp(const float* __restrict__ L,
                                             const int* __restrict__ x) {
    __shared__ float Pt[NK][NM + 1];   // transposed softmax tile, padded
    int v = blockIdx.x;
    if (v < 4) g_m[v * 256 + threadIdx.x] = 0.0f;
    int warp = threadIdx.x >> 5, lane = threadIdx.x & 31;
    // 8 warps x 4 rows each: softmax over 64 logits per row.
#pragma unroll
    for (int i = 0; i < 4; i++) {
        int m = warp * 4 + i;
        const float* lr = L + (v * NM + m) * NK;
        float v0 = lr[lane], v1 = lr[lane + 32];
        float mx = fmaxf(v0, v1);
#pragma unroll
        for (int o = 16; o; o >>= 1) mx = fmaxf(mx, __shfl_xor_sync(0xffffffffu, mx, o));
        float e0 = __expf(v0 - mx), e1 = __expf(v1 - mx);
        float sm = e0 + e1;
#pragma unroll
        for (int o = 16; o; o >>= 1) sm += __shfl_xor_sync(0xffffffffu, sm, o);
        float inv = __frcp_rn(sm);
        Pt[lane][m]      = e0 * inv;
        Pt[lane + 32][m] = e1 * inv;
    }
    __syncthreads();
#pragma unroll
    for (int j = 0; j < 2; j++) {
        int b = (threadIdx.x + j * 256) * 2;          // columns b, b+1
        int i0 = x[b * NV + v];
        int i1 = x[(b + 1) * NV + v];
        unsigned* o = (unsigned*)((unsigned short*)(g_bf + LIN0)
                                  + (unsigned)(v * NM) * BATCH + b);
#pragma unroll
        for (int m = 0; m < NM; m++)
            o[m * (BATCH / 2)] = pack_bf2(Pt[i0][m], Pt[i1][m]);
    }
}

// Prod layer: em[e,b] = prev[p0,b]*prev[p1,b] (* 1/m2^2 when renormalizing).
// 128-thread blocks, 2 elements per block (grid = E/2). The 4 pids arrive as
// ONE broadcast uint4 load; the 4 row loads (64B/thread) are independent.
__global__ void __launch_bounds__(128) k_prod(unsigned em_off, unsigned prev_off,
                                              const int* __restrict__ pids, int start,
                                              int use_m) {
    int t = threadIdx.x;
    unsigned e = blockIdx.x * 2;
    uint4 pv = __ldg((const uint4*)pids + blockIdx.x);   // p00 p01 p10 p11
    int p00 = (int)pv.x - start, p01 = (int)pv.y - start;
    int p10 = (int)pv.z - start, p11 = (int)pv.w - start;
    const uint4* prev = (const uint4*)(g_bf + prev_off);
    uint4 ua0 = prev[(unsigned)p00 * 128 + t];
    uint4 ub0 = prev[(unsigned)p01 * 128 + t];
    uint4 ua1 = prev[(unsigned)p10 * 128 + t];
    uint4 ub1 = prev[(unsigned)p11 * 128 + t];
    float inv[8];
    if (use_m) {
        const float4* mm = (const float4*)g_m;
        float4 m0 = mm[2 * t], m1 = mm[2 * t + 1];
        inv[0] = __frcp_rn(m0.x * m0.x);  inv[1] = __frcp_rn(m0.y * m0.y);
        inv[2] = __frcp_rn(m0.z * m0.z);  inv[3] = __frcp_rn(m0.w * m0.w);
        inv[4] = __frcp_rn(m1.x * m1.x);  inv[5] = __frcp_rn(m1.y * m1.y);
        inv[6] = __frcp_rn(m1.z * m1.z);  inv[7] = __frcp_rn(m1.w * m1.w);
    }
    float r0[8], r1[8];
    r0[0] = lo_bf(ua0.x) * lo_bf(ub0.x);  r0[1] = hi_bf(ua0.x) * hi_bf(ub0.x);
    r0[2] = lo_bf(ua0.y) * lo_bf(ub0.y);  r0[3] = hi_bf(ua0.y) * hi_bf(ub0.y);
    r0[4] = lo_bf(ua0.z) * lo_bf(ub0.z);  r0[5] = hi_bf(ua0.z) * hi_bf(ub0.z);
    r0[6] = lo_bf(ua0.w) * lo_bf(ub0.w);  r0[7] = hi_bf(ua0.w) * hi_bf(ub0.w);
    r1[0] = lo_bf(ua1.x) * lo_bf(ub1.x);  r1[1] = hi_bf(ua1.x) * hi_bf(ub1.x);
    r1[2] = lo_bf(ua1.y) * lo_bf(ub1.y);  r1[3] = hi_bf(ua1.y) * hi_bf(ub1.y);
    r1[4] = lo_bf(ua1.z) * lo_bf(ub1.z);  r1[5] = hi_bf(ua1.z) * hi_bf(ub1.z);
    r1[6] = lo_bf(ua1.w) * lo_bf(ub1.w);  r1[7] = hi_bf(ua1.w) * hi_bf(ub1.w);
    if (use_m) {
#pragma unroll
        for (int j = 0; j < 8; j++) { r0[j] *= inv[j]; r1[j] *= inv[j]; }
    }
    uint4* out = (uint4*)(g_bf + em_off);
    uint4 o0, o1;
    o0.x = pack_bf2(r0[0], r0[1]);  o0.y = pack_bf2(r0[2], r0[3]);
    o0.z = pack_bf2(r0[4], r0[5]);  o0.w = pack_bf2(r0[6], r0[7]);
    o1.x = pack_bf2(r1[0], r1[1]);  o1.y = pack_bf2(r1[2], r1[3]);
    o1.z = pack_bf2(r1[4], r1[5]);  o1.w = pack_bf2(r1[6], r1[7]);
    out[e * 128 + t]       = o0;
    out[(e + 1) * 128 + t] = o1;
}

// Sum layer: out[s,b] = sum_c softmax(w[s])[c] * em[cids[s,c]-1, b].
// One block per sum node; 128 threads x 8 bf16 cover the batch. fp32 acc.
__global__ void __launch_bounds__(128) k_sum(unsigned out_off, unsigned em_off,
                                             const int* __restrict__ cids,
                                             const float* __restrict__ w) {
    __shared__ uint2 swc[32];
    int s = blockIdx.x, t = threadIdx.x;
    if (t < 32) {
        float wv = w[s * 32 + t];
        float mx = wv;
#pragma unroll
        for (int o = 16; o; o >>= 1) mx = fmaxf(mx, __shfl_xor_sync(0xffffffffu, mx, o));
        float e = __expf(wv - mx);
        float sm = e;
#pragma unroll
        for (int o = 16; o; o >>= 1) sm += __shfl_xor_sync(0xffffffffu, sm, o);
        unsigned off = (unsigned)(cids[s * 32 + t] - 1) * 2048u;  // byte offset of row
        swc[t] = make_uint2(__float_as_uint(e * __frcp_rn(sm)), off);
    }
    __syncthreads();
    const char* base = (const char*)(g_bf + em_off) + t * 16;
    float a0 = 0.f, a1 = 0.f, a2 = 0.f, a3 = 0.f;
    float a4 = 0.f, a5 = 0.f, a6 = 0.f, a7 = 0.f;
#pragma unroll
    for (int c = 0; c < 32; c++) {
        uint2 wc = swc[c];
        uint4 u = *(const uint4*)(base + wc.y);
        float wv = __uint_as_float(wc.x);
        a0 = fmaf(wv, lo_bf(u.x), a0);  a1 = fmaf(wv, hi_bf(u.x), a1);
        a2 = fmaf(wv, lo_bf(u.y), a2);  a3 = fmaf(wv, hi_bf(u.y), a3);
        a4 = fmaf(wv, lo_bf(u.z), a4);  a5 = fmaf(wv, hi_bf(u.z), a5);
        a6 = fmaf(wv, lo_bf(u.w), a6);  a7 = fmaf(wv, hi_bf(u.w), a7);
    }
    uint4 o;
    o.x = pack_bf2(a0, a1);  o.y = pack_bf2(a2, a3);
    o.z = pack_bf2(a4, a5);  o.w = pack_bf2(a6, a7);
    ((uint4*)(g_bf + out_off))[s * 128 + t] = o;
}

// Per-batch-column max over S rows (bf16 source). grid (4 b-tiles, 32 s-chunks).
__global__ void __launch_bounds__(256) k_max(unsigned s_off, int rows_per) {
    int b = (blockIdx.x << 8) + threadIdx.x;
    const unsigned short* sr =
        (const unsigned short*)g_bf + s_off + (unsigned)blockIdx.y * rows_per * BATCH + b;
    float loc = 0.0f;
#pragma unroll 8
    for (int i = 0; i < rows_per; i++)
        loc = fmaxf(loc, __uint_as_float((unsigned)sr[i * BATCH] << 16));
    atomicMax(reinterpret_cast<int*>(g_m + b), __float_as_int(loc));
}

// Root: fused layer-4 prod + root sum. Only the 32 referenced elements are
// computed: acc = sum_c w4_c * s3[p0_c]*s3[p1_c];  out = log(acc) + 4*log m2.
__global__ void __launch_bounds__(256) k_root(float* __restrict__ out,
                                              const int* __restrict__ cids,
                                              const int* __restrict__ pids,
                                              const float* __restrict__ w) {
    __shared__ float sw[32];
    __shared__ int   sp0[32], sp1[32];
    int t = threadIdx.x;
    if (t < 32) {
        float wv = w[t];
        float mx = wv;
#pragma unroll
        for (int o = 16; o; o >>= 1) mx = fmaxf(mx, __shfl_xor_sync(0xffffffffu, mx, o));
        float e = __expf(wv - mx);
        float sm = e;
#pragma unroll
        for (int o = 16; o; o >>= 1) sm += __shfl_xor_sync(0xffffffffu, sm, o);
        sw[t] = e * __frcp_rn(sm);
        int elem = cids[t] - 1;                    // pids4 row of this element
        const int start4 = 1 + 8192 + 4096 + 2048; // s3 global-id base
        sp0[t] = __ldg(&pids[elem * 2])     - start4;
        sp1[t] = __ldg(&pids[elem * 2 + 1]) - start4;
    }
    __syncthreads();
    const uint2* s3 = (const uint2*)(g_bf + S3O);
    float a0 = 0.f, a1 = 0.f, a2 = 0.f, a3 = 0.f;
#pragma unroll
    for (int c = 0; c < 32; c++) {
        uint2 u0 = s3[(unsigned)sp0[c] * 256 + t];
        uint2 u1 = s3[(unsigned)sp1[c] * 256 + t];
        float wv = sw[c];
        a0 = fmaf(wv, lo_bf(u0.x) * lo_bf(u1.x), a0);
        a1 = fmaf(wv, hi_bf(u0.x) * hi_bf(u1.x), a1);
        a2 = fmaf(wv, lo_bf(u0.y) * lo_bf(u1.y), a2);
        a3 = fmaf(wv, hi_bf(u0.y) * hi_bf(u1.y), a3);
    }
    const float4* m2 = (const float4*)g_m;
    float4 b2 = m2[t];
    float4 o;
    o.x = logf(a0) + 4.f * logf(b2.x);
    o.y = logf(a1) + 4.f * logf(b2.y);
    o.z = logf(a2) + 4.f * logf(b2.z);
    o.w = logf(a3) + 4.f * logf(b2.w);
    ((float4*)out)[t] = o;
}

extern "C" void kernel_launch(void* const* d_in, const int* in_sizes, int n_in,
                              void* d_out, int out_size) {
    const int*   x      = (const int*)d_in[0];
    const float* logits = (const float*)d_in[1];
    const float* w1     = (const float*)d_in[2];
    const float* w2     = (const float*)d_in[3];
    const float* w3     = (const float*)d_in[4];
    const float* w4     = (const float*)d_in[5];
    const int*   pids1  = (const int*)d_in[6];
    const int*   pids2  = (const int*)d_in[7];
    const int*   pids3  = (const int*)d_in[8];
    const int*   pids4  = (const int*)d_in[9];
    const int*   cids1  = (const int*)d_in[10];
    const int*   cids2  = (const int*)d_in[11];
    const int*   cids3  = (const int*)d_in[12];
    const int*   cids4  = (const int*)d_in[13];

    k_inp<<<NV, 256>>>(logits, x);             // fused softmax+gather, zeros g_m

    // Layer 1: prod from inputs (global ids start at 1).
    k_prod<<<8192 / 2, 128>>>(EMO, LIN0, pids1, 1, 0);
    k_sum<<<4096, 128>>>(S1O, EMO, cids1, w1);

    // Layer 2: prod from s1 (ids start 8193). s1 range safe in bf16 -> no renorm.
    k_prod<<<4096 / 2, 128>>>(EMO, S1O, pids2, 1 + 8192, 0);
    k_sum<<<2048, 128>>>(S2O, EMO, cids2, w2);
    k_max<<<dim3(4, 32), 256>>>(S2O, 2048 / 32);

    // Layer 3: prod from s2 (ids start 12289), renormalize by m2.
    k_prod<<<2048 / 2, 128>>>(EMO, S2O, pids3, 1 + 8192 + 4096, 1);
    k_sum<<<1024, 128>>>(S3O, EMO, cids3, w3);

    // Layer 4 (prod+sum) fused into the root kernel.
    k_root<<<1, 256>>>((float*)d_out, cids4, pids4, w4);
}

// round 12
// speedup vs baseline: 1.4059x; 1.4059x over previous
#include <cuda_runtime.h>
#include <cuda_bf16.h>

// ---------------------------------------------------------------------------
// TensorCircuit forward, linear domain, bf16 activation storage.
//   input:  lin0[i,b] = softmax(in_logits[i])[x[b, i/32]]         (bf16)
//   prod l: em[e,b]   = prev[p0,b]*prev[p1,b] (/ m2^2 at layer 3) (bf16)
//   sum  l: s[s,b]    = sum_c softmax(w[s])[c] * em[cid,b]        (bf16, fp32 acc)
//   renorm: single per-batch-column max m2 after s2
//   layer4 prod+sum collapsed into k_root (only 32 of 1024 elements used).
//   root   = log( sum_c w4_c * s3[p0_c]*s3[p1_c] ) + 4*log m2     (fp32)
// ---------------------------------------------------------------------------

#define BATCH 1024
#define NV    256
#define NK    64
#define NM    32
#define NN0   8192

// bf16 arena (element offsets). All offsets are multiples of 1024 -> 16B aligned.
#define LIN0  0u
#define EMO   (8192u * 1024u)
#define S1O   (EMO + 8192u * 1024u)
#define S2O   (S1O + 4096u * 1024u)
#define S3O   (S2O + 2048u * 1024u)
#define BF_SZ (S3O + 1024u * 1024u)

__device__ __nv_bfloat16 g_bf[BF_SZ];
__device__ float g_m[BATCH];        // per-column renorm max m2 (fp32)

// --- bf16 bit-trick helpers -------------------------------------------------
__device__ __forceinline__ float lo_bf(unsigned u) { return __uint_as_float(u << 16); }
__device__ __forceinline__ float hi_bf(unsigned u) { return __uint_as_float(u & 0xffff0000u); }
__device__ __forceinline__ unsigned pack_bf2(float lo, float hi) {
    unsigned r;
    asm("cvt.rn.bf16x2.f32 %0, %1, %2;" : "=r"(r) : "f"(hi), "f"(lo));
    return r;
}

// Fused input layer: per-variable block computes the 32-row softmax tile in
// smem (transposed, padded), then each thread gathers for a COLUMN PAIR and
// writes packed bf16x2 -> full 128B store wavefronts. Blocks 0..3 zero g_m.
__global__ void __launch_bounds__(256) k_inp(const float* __restrict__ L,
                                             const int* __restrict__ x) {
    __shared__ float Pt[NK][NM + 1];   // transposed softmax tile, padded
    int v = blockIdx.x;
    if (v < 4) g_m[v * 256 + threadIdx.x] = 0.0f;
    int warp = threadIdx.x >> 5, lane = threadIdx.x & 31;
    // 8 warps x 4 rows each: softmax over 64 logits per row.
#pragma unroll
    for (int i = 0; i < 4; i++) {
        int m = warp * 4 + i;
        const float* lr = L + (v * NM + m) * NK;
        float v0 = lr[lane], v1 = lr[lane + 32];
        float mx = fmaxf(v0, v1);
#pragma unroll
        for (int o = 16; o; o >>= 1) mx = fmaxf(mx, __shfl_xor_sync(0xffffffffu, mx, o));
        float e0 = __expf(v0 - mx), e1 = __expf(v1 - mx);
        float sm = e0 + e1;
#pragma unroll
        for (int o = 16; o; o >>= 1) sm += __shfl_xor_sync(0xffffffffu, sm, o);
        float inv = __frcp_rn(sm);
        Pt[lane][m]      = e0 * inv;
        Pt[lane + 32][m] = e1 * inv;
    }
    __syncthreads();
#pragma unroll
    for (int j = 0; j < 2; j++) {
        int b = (threadIdx.x + j * 256) * 2;          // columns b, b+1
        int i0 = x[b * NV + v];
        int i1 = x[(b + 1) * NV + v];
        unsigned* o = (unsigned*)((unsigned short*)(g_bf + LIN0)
                                  + (unsigned)(v * NM) * BATCH + b);
#pragma unroll
        for (int m = 0; m < NM; m++)
            o[m * (BATCH / 2)] = pack_bf2(Pt[i0][m], Pt[i1][m]);
    }
}

// Prod layer (R9 configuration): em[e,b] = prev[p0,b]*prev[p1,b] (* 1/m2^2).
// 256 threads = 2 half-blocks of 128; each half handles 2 elements, fully
// unrolled: all 4 pid loads then all 4 row loads issued back-to-back.
// grid = E/4.
__global__ void __launch_bounds__(256) k_prod(unsigned em_off, unsigned prev_off,
                                              const int* __restrict__ pids, int start,
                                              int use_m) {
    int tid = threadIdx.x;
    int half = tid >> 7, t = tid & 127;
    unsigned e0 = blockIdx.x * 4 + half;              // this half's elements: e0, e0+2
    const int* pp = pids + e0 * 2;
    int p00 = __ldg(pp)     - start;
    int p01 = __ldg(pp + 1) - start;
    int p10 = __ldg(pp + 4) - start;
    int p11 = __ldg(pp + 5) - start;
    const uint4* prev = (const uint4*)(g_bf + prev_off);
    uint4 ua0 = prev[(unsigned)p00 * 128 + t];
    uint4 ub0 = prev[(unsigned)p01 * 128 + t];
    uint4 ua1 = prev[(unsigned)p10 * 128 + t];
    uint4 ub1 = prev[(unsigned)p11 * 128 + t];
    float inv[8];
    if (use_m) {
        const float4* mm = (const float4*)g_m;
        float4 m0 = mm[2 * t], m1 = mm[2 * t + 1];
        inv[0] = __frcp_rn(m0.x * m0.x);  inv[1] = __frcp_rn(m0.y * m0.y);
        inv[2] = __frcp_rn(m0.z * m0.z);  inv[3] = __frcp_rn(m0.w * m0.w);
        inv[4] = __frcp_rn(m1.x * m1.x);  inv[5] = __frcp_rn(m1.y * m1.y);
        inv[6] = __frcp_rn(m1.z * m1.z);  inv[7] = __frcp_rn(m1.w * m1.w);
    }
    float r0[8], r1[8];
    r0[0] = lo_bf(ua0.x) * lo_bf(ub0.x);  r0[1] = hi_bf(ua0.x) * hi_bf(ub0.x);
    r0[2] = lo_bf(ua0.y) * lo_bf(ub0.y);  r0[3] = hi_bf(ua0.y) * hi_bf(ub0.y);
    r0[4] = lo_bf(ua0.z) * lo_bf(ub0.z);  r0[5] = hi_bf(ua0.z) * hi_bf(ub0.z);
    r0[6] = lo_bf(ua0.w) * lo_bf(ub0.w);  r0[7] = hi_bf(ua0.w) * hi_bf(ub0.w);
    r1[0] = lo_bf(ua1.x) * lo_bf(ub1.x);  r1[1] = hi_bf(ua1.x) * hi_bf(ub1.x);
    r1[2] = lo_bf(ua1.y) * lo_bf(ub1.y);  r1[3] = hi_bf(ua1.y) * hi_bf(ub1.y);
    r1[4] = lo_bf(ua1.z) * lo_bf(ub1.z);  r1[5] = hi_bf(ua1.z) * hi_bf(ub1.z);
    r1[6] = lo_bf(ua1.w) * lo_bf(ub1.w);  r1[7] = hi_bf(ua1.w) * hi_bf(ub1.w);
    if (use_m) {
#pragma unroll
        for (int j = 0; j < 8; j++) { r0[j] *= inv[j]; r1[j] *= inv[j]; }
    }
    uint4* out = (uint4*)(g_bf + em_off);
    uint4 o0, o1;
    o0.x = pack_bf2(r0[0], r0[1]);  o0.y = pack_bf2(r0[2], r0[3]);
    o0.z = pack_bf2(r0[4], r0[5]);  o0.w = pack_bf2(r0[6], r0[7]);
    o1.x = pack_bf2(r1[0], r1[1]);  o1.y = pack_bf2(r1[2], r1[3]);
    o1.z = pack_bf2(r1[4], r1[5]);  o1.w = pack_bf2(r1[6], r1[7]);
    out[e0 * 128 + t]       = o0;
    out[(e0 + 2) * 128 + t] = o1;
}

// Sum layer (full-batch form, layer 1): out[s,b] = sum_c w~[s,c]*em[cid,b].
// One block per sum node; 128 threads x 8 bf16 cover the batch. fp32 acc.
__global__ void __launch_bounds__(128) k_sum(unsigned out_off, unsigned em_off,
                                             const int* __restrict__ cids,
                                             const float* __restrict__ w) {
    __shared__ uint2 swc[32];
    int s = blockIdx.x, t = threadIdx.x;
    if (t < 32) {
        float wv = w[s * 32 + t];
        float mx = wv;
#pragma unroll
        for (int o = 16; o; o >>= 1) mx = fmaxf(mx, __shfl_xor_sync(0xffffffffu, mx, o));
        float e = __expf(wv - mx);
        float sm = e;
#pragma unroll
        for (int o = 16; o; o >>= 1) sm += __shfl_xor_sync(0xffffffffu, sm, o);
        unsigned off = (unsigned)(cids[s * 32 + t] - 1) * 2048u;  // byte offset of row
        swc[t] = make_uint2(__float_as_uint(e * __frcp_rn(sm)), off);
    }
    __syncthreads();
    const char* base = (const char*)(g_bf + em_off) + t * 16;
    float a0 = 0.f, a1 = 0.f, a2 = 0.f, a3 = 0.f;
    float a4 = 0.f, a5 = 0.f, a6 = 0.f, a7 = 0.f;
#pragma unroll
    for (int c = 0; c < 32; c++) {
        uint2 wc = swc[c];
        uint4 u = *(const uint4*)(base + wc.y);
        float wv = __uint_as_float(wc.x);
        a0 = fmaf(wv, lo_bf(u.x), a0);  a1 = fmaf(wv, hi_bf(u.x), a1);
        a2 = fmaf(wv, lo_bf(u.y), a2);  a3 = fmaf(wv, hi_bf(u.y), a3);
        a4 = fmaf(wv, lo_bf(u.z), a4);  a5 = fmaf(wv, hi_bf(u.z), a5);
        a6 = fmaf(wv, lo_bf(u.w), a6);  a7 = fmaf(wv, hi_bf(u.w), a7);
    }
    uint4 o;
    o.x = pack_bf2(a0, a1);  o.y = pack_bf2(a2, a3);
    o.z = pack_bf2(a4, a5);  o.w = pack_bf2(a6, a7);
    ((uint4*)(g_bf + out_off))[s * 128 + t] = o;
}

// Sum layer (batch-split form, layers 2-3): grid=(S, 2); each block handles a
// 1KB half of the batch row via uint2 loads. Doubles block count for the
// small, latency-bound layers; traffic and per-column accumulation order
// are unchanged.
__global__ void __launch_bounds__(128) k_sum2(unsigned out_off, unsigned em_off,
                                              const int* __restrict__ cids,
                                              const float* __restrict__ w) {
    __shared__ uint2 swc[32];
    int s = blockIdx.x, t = threadIdx.x;
    unsigned hoff = blockIdx.y * 1024u;          // byte offset of batch half
    if (t < 32) {
        float wv = w[s * 32 + t];
        float mx = wv;
#pragma unroll
        for (int o = 16; o; o >>= 1) mx = fmaxf(mx, __shfl_xor_sync(0xffffffffu, mx, o));
        float e = __expf(wv - mx);
        float sm = e;
#pragma unroll
        for (int o = 16; o; o >>= 1) sm += __shfl_xor_sync(0xffffffffu, sm, o);
        unsigned off = (unsigned)(cids[s * 32 + t] - 1) * 2048u;
        swc[t] = make_uint2(__float_as_uint(e * __frcp_rn(sm)), off);
    }
    __syncthreads();
    const char* base = (const char*)(g_bf + em_off) + hoff + t * 8;
    float a0 = 0.f, a1 = 0.f, a2 = 0.f, a3 = 0.f;
#pragma unroll
    for (int c = 0; c < 32; c++) {
        uint2 wc = swc[c];
        uint2 u = *(const uint2*)(base + wc.y);
        float wv = __uint_as_float(wc.x);
        a0 = fmaf(wv, lo_bf(u.x), a0);  a1 = fmaf(wv, hi_bf(u.x), a1);
        a2 = fmaf(wv, lo_bf(u.y), a2);  a3 = fmaf(wv, hi_bf(u.y), a3);
    }
    uint2 o;
    o.x = pack_bf2(a0, a1);  o.y = pack_bf2(a2, a3);
    *(uint2*)((char*)(g_bf + out_off) + s * 2048u + hoff + t * 8) = o;
}

// Per-batch-column max over S rows (bf16 source). grid (4 b-tiles, 32 s-chunks).
__global__ void __launch_bounds__(256) k_max(unsigned s_off, int rows_per) {
    int b = (blockIdx.x << 8) + threadIdx.x;
    const unsigned short* sr =
        (const unsigned short*)g_bf + s_off + (unsigned)blockIdx.y * rows_per * BATCH + b;
    float loc = 0.0f;
#pragma unroll 8
    for (int i = 0; i < rows_per; i++)
        loc = fmaxf(loc, __uint_as_float((unsigned)sr[i * BATCH] << 16));
    atomicMax(reinterpret_cast<int*>(g_m + b), __float_as_int(loc));
}

// Root: fused layer-4 prod + root sum. Only the 32 referenced elements are
// computed: acc = sum_c w4_c * s3[p0_c]*s3[p1_c];  out = log(acc) + 4*log m2.
__global__ void __launch_bounds__(256) k_root(float* __restrict__ out,
                                              const int* __restrict__ cids,
                                              const int* __restrict__ pids,
                                              const float* __restrict__ w) {
    __shared__ float sw[32];
    __shared__ int   sp0[32], sp1[32];
    int t = threadIdx.x;
    if (t < 32) {
        float wv = w[t];
        float mx = wv;
#pragma unroll
        for (int o = 16; o; o >>= 1) mx = fmaxf(mx, __shfl_xor_sync(0xffffffffu, mx, o));
        float e = __expf(wv - mx);
        float sm = e;
#pragma unroll
        for (int o = 16; o; o >>= 1) sm += __shfl_xor_sync(0xffffffffu, sm, o);
        sw[t] = e * __frcp_rn(sm);
        int elem = cids[t] - 1;                    // pids4 row of this element
        const int start4 = 1 + 8192 + 4096 + 2048; // s3 global-id base
        sp0[t] = __ldg(&pids[elem * 2])     - start4;
        sp1[t] = __ldg(&pids[elem * 2 + 1]) - start4;
    }
    __syncthreads();
    const uint2* s3 = (const uint2*)(g_bf + S3O);
    float a0 = 0.f, a1 = 0.f, a2 = 0.f, a3 = 0.f;
#pragma unroll
    for (int c = 0; c < 32; c++) {
        uint2 u0 = s3[(unsigned)sp0[c] * 256 + t];
        uint2 u1 = s3[(unsigned)sp1[c] * 256 + t];
        float wv = sw[c];
        a0 = fmaf(wv, lo_bf(u0.x) * lo_bf(u1.x), a0);
        a1 = fmaf(wv, hi_bf(u0.x) * hi_bf(u1.x), a1);
        a2 = fmaf(wv, lo_bf(u0.y) * lo_bf(u1.y), a2);
        a3 = fmaf(wv, hi_bf(u0.y) * hi_bf(u1.y), a3);
    }
    const float4* m2 = (const float4*)g_m;
    float4 b2 = m2[t];
    float4 o;
    o.x = logf(a0) + 4.f * logf(b2.x);
    o.y = logf(a1) + 4.f * logf(b2.y);
    o.z = logf(a2) + 4.f * logf(b2.z);
    o.w = logf(a3) + 4.f * logf(b2.w);
    ((float4*)out)[t] = o;
}

extern "C" void kernel_launch(void* const* d_in, const int* in_sizes, int n_in,
                              void* d_out, int out_size) {
    const int*   x      = (const int*)d_in[0];
    const float* logits = (const float*)d_in[1];
    const float* w1     = (const float*)d_in[2];
    const float* w2     = (const float*)d_in[3];
    const float* w3     = (const float*)d_in[4];
    const float* w4     = (const float*)d_in[5];
    const int*   pids1  = (const int*)d_in[6];
    const int*   pids2  = (const int*)d_in[7];
    const int*   pids3  = (const int*)d_in[8];
    const int*   pids4  = (const int*)d_in[9];
    const int*   cids1  = (const int*)d_in[10];
    const int*   cids2  = (const int*)d_in[11];
    const int*   cids3  = (const int*)d_in[12];
    const int*   cids4  = (const int*)d_in[13];

    k_inp<<<NV, 256>>>(logits, x);             // fused softmax+gather, zeros g_m

    // Layer 1: prod from inputs (global ids start at 1).
    k_prod<<<8192 / 4, 256>>>(EMO, LIN0, pids1, 1, 0);
    k_sum<<<4096, 128>>>(S1O, EMO, cids1, w1);

    // Layer 2: prod from s1 (ids start 8193). s1 range safe in bf16 -> no renorm.
    k_prod<<<4096 / 4, 256>>>(EMO, S1O, pids2, 1 + 8192, 0);
    k_sum2<<<dim3(2048, 2), 128>>>(S2O, EMO, cids2, w2);
    k_max<<<dim3(4, 32), 256>>>(S2O, 2048 / 32);

    // Layer 3: prod from s2 (ids start 12289), renormalize by m2.
    k_prod<<<2048 / 4, 256>>>(EMO, S2O, pids3, 1 + 8192 + 4096, 1);
    k_sum2<<<dim3(1024, 2), 128>>>(S3O, EMO, cids3, w3);

    // Layer 4 (prod+sum) fused into the root kernel.
    k_root<<<1, 256>>>((float*)d_out, cids4, pids4, w4);
}

// round 13
// speedup vs baseline: 1.5870x; 1.1289x over previous
#include <cuda_runtime.h>
#include <cuda_bf16.h>
#include <cuda_fp16.h>

// ---------------------------------------------------------------------------
// TensorCircuit forward, linear domain.
//   input:  lin0[i,b] = softmax(in_logits[i])[x[b, i/32]]          (bf16)
//   prod1:  em1[e,b]  = lin0[p0,b]*lin0[p1,b] * 2^14               (fp8 e5m2)
//   sum1:   s1[s,b]   = 2^-14 * sum_c w~[s,c]*em1[cid,b]           (bf16, f16x2 acc)
//   prod2:  em[e,b]   = s1[p0]*s1[p1]                              (bf16)
//   sum2:   s2        = gathered weighted dot                      (bf16, fp32 acc)
//   renorm: per-column max m2 of s2
//   prod3:  em = s2[p0]*s2[p1]/m2^2 ; sum3 -> s3                   (bf16)
//   layer4 prod+sum collapsed into k_root (only 32 of 1024 elements used).
//   root   = log( sum_c w4_c * s3[p0_c]*s3[p1_c] ) + 4*log m2      (fp32)
// ---------------------------------------------------------------------------

#define BATCH 1024
#define NV    256
#define NK    64
#define NM    32
#define NN0   8192

// bf16 arena (element offsets).
#define LIN0  0u
#define EMO   (8192u * 1024u)
#define S1O   (EMO + 8192u * 1024u)
#define S2O   (S1O + 4096u * 1024u)
#define S3O   (S2O + 2048u * 1024u)
#define BF_SZ (S3O + 1024u * 1024u)

__device__ __nv_bfloat16 g_bf[BF_SZ];
__device__ unsigned char g_e8[8192u * 1024u];   // em1, fp8 e5m2 (scaled 2^14)
__device__ float g_m[BATCH];                     // per-column renorm max m2

#define EM1_SCALE    16384.0f
#define EM1_INVSCALE (1.0f / 16384.0f)

// --- packing helpers ---------------------------------------------------------
__device__ __forceinline__ float lo_bf(unsigned u) { return __uint_as_float(u << 16); }
__device__ __forceinline__ float hi_bf(unsigned u) { return __uint_as_float(u & 0xffff0000u); }
__device__ __forceinline__ unsigned pack_bf2(float lo, float hi) {
    unsigned r;
    asm("cvt.rn.bf16x2.f32 %0, %1, %2;" : "=r"(r) : "f"(hi), "f"(lo));
    return r;
}
// pack 2 floats -> e5m2x2 (low byte = lo)
__device__ __forceinline__ unsigned short pack_e5(float lo, float hi) {
    unsigned short r;
    asm("cvt.rn.satfinite.e5m2x2.f32 %0, %1, %2;" : "=h"(r) : "f"(hi), "f"(lo));
    return r;
}
// unpack e5m2x2 -> f16x2 (low byte -> low half)
__device__ __forceinline__ __half2 unpack_e5(unsigned short v) {
    unsigned r;
    asm("cvt.rn.f16x2.e5m2x2 %0, %1;" : "=r"(r) : "h"(v));
    return *(__half2*)&r;
}

// Fused input layer: per-variable block computes the 32-row softmax tile in
// smem (transposed, padded), then each thread gathers for a COLUMN PAIR and
// writes packed bf16x2. Blocks 0..3 zero g_m.
__global__ void __launch_bounds__(256) k_inp(const float* __restrict__ L,
                                             const int* __restrict__ x) {
    __shared__ float Pt[NK][NM + 1];
    int v = blockIdx.x;
    if (v < 4) g_m[v * 256 + threadIdx.x] = 0.0f;
    int warp = threadIdx.x >> 5, lane = threadIdx.x & 31;
#pragma unroll
    for (int i = 0; i < 4; i++) {
        int m = warp * 4 + i;
        const float* lr = L + (v * NM + m) * NK;
        float v0 = lr[lane], v1 = lr[lane + 32];
        float mx = fmaxf(v0, v1);
#pragma unroll
        for (int o = 16; o; o >>= 1) mx = fmaxf(mx, __shfl_xor_sync(0xffffffffu, mx, o));
        float e0 = __expf(v0 - mx), e1 = __expf(v1 - mx);
        float sm = e0 + e1;
#pragma unroll
        for (int o = 16; o; o >>= 1) sm += __shfl_xor_sync(0xffffffffu, sm, o);
        float inv = __frcp_rn(sm);
        Pt[lane][m]      = e0 * inv;
        Pt[lane + 32][m] = e1 * inv;
    }
    __syncthreads();
#pragma unroll
    for (int j = 0; j < 2; j++) {
        int b = (threadIdx.x + j * 256) * 2;
        int i0 = x[b * NV + v];
        int i1 = x[(b + 1) * NV + v];
        unsigned* o = (unsigned*)((unsigned short*)(g_bf + LIN0)
                                  + (unsigned)(v * NM) * BATCH + b);
#pragma unroll
        for (int m = 0; m < NM; m++)
            o[m * (BATCH / 2)] = pack_bf2(Pt[i0][m], Pt[i1][m]);
    }
}

// Layer-1 prod: em1[e,b] = lin0[p0,b]*lin0[p1,b] * 2^14, stored fp8 e5m2.
// 256 threads = 2 halves of 128; each half 2 elements (grid = E/4).
__global__ void __launch_bounds__(256) k_prod8(const int* __restrict__ pids) {
    int tid = threadIdx.x;
    int half = tid >> 7, t = tid & 127;
    unsigned e0 = blockIdx.x * 4 + half;          // elements e0, e0+2
    const int* pp = pids + e0 * 2;
    int p00 = __ldg(pp)     - 1;
    int p01 = __ldg(pp + 1) - 1;
    int p10 = __ldg(pp + 4) - 1;
    int p11 = __ldg(pp + 5) - 1;
    const uint4* prev = (const uint4*)(g_bf + LIN0);
    uint4 ua0 = prev[(unsigned)p00 * 128 + t];
    uint4 ub0 = prev[(unsigned)p01 * 128 + t];
    uint4 ua1 = prev[(unsigned)p10 * 128 + t];
    uint4 ub1 = prev[(unsigned)p11 * 128 + t];
    float r0[8], r1[8];
    r0[0] = lo_bf(ua0.x) * lo_bf(ub0.x);  r0[1] = hi_bf(ua0.x) * hi_bf(ub0.x);
    r0[2] = lo_bf(ua0.y) * lo_bf(ub0.y);  r0[3] = hi_bf(ua0.y) * hi_bf(ub0.y);
    r0[4] = lo_bf(ua0.z) * lo_bf(ub0.z);  r0[5] = hi_bf(ua0.z) * hi_bf(ub0.z);
    r0[6] = lo_bf(ua0.w) * lo_bf(ub0.w);  r0[7] = hi_bf(ua0.w) * hi_bf(ub0.w);
    r1[0] = lo_bf(ua1.x) * lo_bf(ub1.x);  r1[1] = hi_bf(ua1.x) * hi_bf(ub1.x);
    r1[2] = lo_bf(ua1.y) * lo_bf(ub1.y);  r1[3] = hi_bf(ua1.y) * hi_bf(ub1.y);
    r1[4] = lo_bf(ua1.z) * lo_bf(ub1.z);  r1[5] = hi_bf(ua1.z) * hi_bf(ub1.z);
    r1[6] = lo_bf(ua1.w) * lo_bf(ub1.w);  r1[7] = hi_bf(ua1.w) * hi_bf(ub1.w);
#pragma unroll
    for (int j = 0; j < 8; j++) { r0[j] *= EM1_SCALE; r1[j] *= EM1_SCALE; }
    uint2 o0, o1;
    o0.x = (unsigned)pack_e5(r0[0], r0[1]) | ((unsigned)pack_e5(r0[2], r0[3]) << 16);
    o0.y = (unsigned)pack_e5(r0[4], r0[5]) | ((unsigned)pack_e5(r0[6], r0[7]) << 16);
    o1.x = (unsigned)pack_e5(r1[0], r1[1]) | ((unsigned)pack_e5(r1[2], r1[3]) << 16);
    o1.y = (unsigned)pack_e5(r1[4], r1[5]) | ((unsigned)pack_e5(r1[6], r1[7]) << 16);
    uint2* out = (uint2*)g_e8;
    out[e0 * 128 + t]       = o0;
    out[(e0 + 2) * 128 + t] = o1;
}

// Layer-1 sum over fp8 em1: s1[s,b] = 2^-14 * sum_c w~[s,c]*em1[cid,b].
// One block per sum node; 128 threads x 8 fp8 columns; f16x2 accumulation.
__global__ void __launch_bounds__(128) k_sum8(const int* __restrict__ cids,
                                              const float* __restrict__ w) {
    __shared__ uint2 swc[32];     // .x = half2(w,w) bits, .y = row byte offset
    int s = blockIdx.x, t = threadIdx.x;
    if (t < 32) {
        float wv = w[s * 32 + t];
        float mx = wv;
#pragma unroll
        for (int o = 16; o; o >>= 1) mx = fmaxf(mx, __shfl_xor_sync(0xffffffffu, mx, o));
        float e = __expf(wv - mx);
        float sm = e;
#pragma unroll
        for (int o = 16; o; o >>= 1) sm += __shfl_xor_sync(0xffffffffu, sm, o);
        __half2 wh = __float2half2_rn(e * __frcp_rn(sm));
        swc[t] = make_uint2(*(unsigned*)&wh, (unsigned)(cids[s * 32 + t] - 1) * 1024u);
    }
    __syncthreads();
    const char* base = (const char*)g_e8 + t * 8;
    __half2 acc0 = __float2half2_rn(0.f), acc1 = acc0, acc2 = acc0, acc3 = acc0;
#pragma unroll
    for (int c = 0; c < 32; c++) {
        uint2 wc = swc[c];
        uint2 u = *(const uint2*)(base + wc.y);
        __half2 wh = *(__half2*)&wc.x;
        acc0 = __hfma2(wh, unpack_e5((unsigned short)(u.x & 0xffffu)), acc0);
        acc1 = __hfma2(wh, unpack_e5((unsigned short)(u.x >> 16)),     acc1);
        acc2 = __hfma2(wh, unpack_e5((unsigned short)(u.y & 0xffffu)), acc2);
        acc3 = __hfma2(wh, unpack_e5((unsigned short)(u.y >> 16)),     acc3);
    }
    float2 v0 = __half22float2(acc0), v1 = __half22float2(acc1);
    float2 v2 = __half22float2(acc2), v3 = __half22float2(acc3);
    uint4 o;
    o.x = pack_bf2(v0.x * EM1_INVSCALE, v0.y * EM1_INVSCALE);
    o.y = pack_bf2(v1.x * EM1_INVSCALE, v1.y * EM1_INVSCALE);
    o.z = pack_bf2(v2.x * EM1_INVSCALE, v2.y * EM1_INVSCALE);
    o.w = pack_bf2(v3.x * EM1_INVSCALE, v3.y * EM1_INVSCALE);
    ((uint4*)(g_bf + S1O))[s * 128 + t] = o;
}

// bf16 prod layer (layers 2-3): em[e,b] = prev[p0,b]*prev[p1,b] (* 1/m2^2).
// 256 threads = 2 halves of 128; each half 2 elements (grid = E/4).
__global__ void __launch_bounds__(256) k_prod(unsigned em_off, unsigned prev_off,
                                              const int* __restrict__ pids, int start,
                                              int use_m) {
    int tid = threadIdx.x;
    int half = tid >> 7, t = tid & 127;
    unsigned e0 = blockIdx.x * 4 + half;
    const int* pp = pids + e0 * 2;
    int p00 = __ldg(pp)     - start;
    int p01 = __ldg(pp + 1) - start;
    int p10 = __ldg(pp + 4) - start;
    int p11 = __ldg(pp + 5) - start;
    const uint4* prev = (const uint4*)(g_bf + prev_off);
    uint4 ua0 = prev[(unsigned)p00 * 128 + t];
    uint4 ub0 = prev[(unsigned)p01 * 128 + t];
    uint4 ua1 = prev[(unsigned)p10 * 128 + t];
    uint4 ub1 = prev[(unsigned)p11 * 128 + t];
    float inv[8];
    if (use_m) {
        const float4* mm = (const float4*)g_m;
        float4 m0 = mm[2 * t], m1 = mm[2 * t + 1];
        inv[0] = __frcp_rn(m0.x * m0.x);  inv[1] = __frcp_rn(m0.y * m0.y);
        inv[2] = __frcp_rn(m0.z * m0.z);  inv[3] = __frcp_rn(m0.w * m0.w);
        inv[4] = __frcp_rn(m1.x * m1.x);  inv[5] = __frcp_rn(m1.y * m1.y);
        inv[6] = __frcp_rn(m1.z * m1.z);  inv[7] = __frcp_rn(m1.w * m1.w);
    }
    float r0[8], r1[8];
    r0[0] = lo_bf(ua0.x) * lo_bf(ub0.x);  r0[1] = hi_bf(ua0.x) * hi_bf(ub0.x);
    r0[2] = lo_bf(ua0.y) * lo_bf(ub0.y);  r0[3] = hi_bf(ua0.y) * hi_bf(ub0.y);
    r0[4] = lo_bf(ua0.z) * lo_bf(ub0.z);  r0[5] = hi_bf(ua0.z) * hi_bf(ub0.z);
    r0[6] = lo_bf(ua0.w) * lo_bf(ub0.w);  r0[7] = hi_bf(ua0.w) * hi_bf(ub0.w);
    r1[0] = lo_bf(ua1.x) * lo_bf(ub1.x);  r1[1] = hi_bf(ua1.x) * hi_bf(ub1.x);
    r1[2] = lo_bf(ua1.y) * lo_bf(ub1.y);  r1[3] = hi_bf(ua1.y) * hi_bf(ub1.y);
    r1[4] = lo_bf(ua1.z) * lo_bf(ub1.z);  r1[5] = hi_bf(ua1.z) * hi_bf(ub1.z);
    r1[6] = lo_bf(ua1.w) * lo_bf(ub1.w);  r1[7] = hi_bf(ua1.w) * hi_bf(ub1.w);
    if (use_m) {
#pragma unroll
        for (int j = 0; j < 8; j++) { r0[j] *= inv[j]; r1[j] *= inv[j]; }
    }
    uint4* out = (uint4*)(g_bf + em_off);
    uint4 o0, o1;
    o0.x = pack_bf2(r0[0], r0[1]);  o0.y = pack_bf2(r0[2], r0[3]);
    o0.z = pack_bf2(r0[4], r0[5]);  o0.w = pack_bf2(r0[6], r0[7]);
    o1.x = pack_bf2(r1[0], r1[1]);  o1.y = pack_bf2(r1[2], r1[3]);
    o1.z = pack_bf2(r1[4], r1[5]);  o1.w = pack_bf2(r1[6], r1[7]);
    out[e0 * 128 + t]       = o0;
    out[(e0 + 2) * 128 + t] = o1;
}

// bf16 sum layer (layers 2-3): out[s,b] = sum_c w~[s,c]*em[cid,b]. fp32 acc.
__global__ void __launch_bounds__(128) k_sum(unsigned out_off, unsigned em_off,
                                             const int* __restrict__ cids,
                                             const float* __restrict__ w) {
    __shared__ uint2 swc[32];
    int s = blockIdx.x, t = threadIdx.x;
    if (t < 32) {
        float wv = w[s * 32 + t];
        float mx = wv;
#pragma unroll
        for (int o = 16; o; o >>= 1) mx = fmaxf(mx, __shfl_xor_sync(0xffffffffu, mx, o));
        float e = __expf(wv - mx);
        float sm = e;
#pragma unroll
        for (int o = 16; o; o >>= 1) sm += __shfl_xor_sync(0xffffffffu, sm, o);
        unsigned off = (unsigned)(cids[s * 32 + t] - 1) * 2048u;
        swc[t] = make_uint2(__float_as_uint(e * __frcp_rn(sm)), off);
    }
    __syncthreads();
    const char* base = (const char*)(g_bf + em_off) + t * 16;
    float a0 = 0.f, a1 = 0.f, a2 = 0.f, a3 = 0.f;
    float a4 = 0.f, a5 = 0.f, a6 = 0.f, a7 = 0.f;
#pragma unroll
    for (int c = 0; c < 32; c++) {
        uint2 wc = swc[c];
        uint4 u = *(const uint4*)(base + wc.y);
        float wv = __uint_as_float(wc.x);
        a0 = fmaf(wv, lo_bf(u.x), a0);  a1 = fmaf(wv, hi_bf(u.x), a1);
        a2 = fmaf(wv, lo_bf(u.y), a2);  a3 = fmaf(wv, hi_bf(u.y), a3);
        a4 = fmaf(wv, lo_bf(u.z), a4);  a5 = fmaf(wv, hi_bf(u.z), a5);
        a6 = fmaf(wv, lo_bf(u.w), a6);  a7 = fmaf(wv, hi_bf(u.w), a7);
    }
    uint4 o;
    o.x = pack_bf2(a0, a1);  o.y = pack_bf2(a2, a3);
    o.z = pack_bf2(a4, a5);  o.w = pack_bf2(a6, a7);
    ((uint4*)(g_bf + out_off))[s * 128 + t] = o;
}

// Per-batch-column max over S rows (bf16 source). grid (4 b-tiles, 32 s-chunks).
__global__ void __launch_bounds__(256) k_max(unsigned s_off, int rows_per) {
    int b = (blockIdx.x << 8) + threadIdx.x;
    const unsigned short* sr =
        (const unsigned short*)g_bf + s_off + (unsigned)blockIdx.y * rows_per * BATCH + b;
    float loc = 0.0f;
#pragma unroll 8
    for (int i = 0; i < rows_per; i++)
        loc = fmaxf(loc, __uint_as_float((unsigned)sr[i * BATCH] << 16));
    atomicMax(reinterpret_cast<int*>(g_m + b), __float_as_int(loc));
}

// Root: fused layer-4 prod + root sum over the 32 referenced elements.
__global__ void __launch_bounds__(256) k_root(float* __restrict__ out,
                                              const int* __restrict__ cids,
                                              const int* __restrict__ pids,
                                              const float* __restrict__ w) {
    __shared__ float sw[32];
    __shared__ int   sp0[32], sp1[32];
    int t = threadIdx.x;
    if (t < 32) {
        float wv = w[t];
        float mx = wv;
#pragma unroll
        for (int o = 16; o; o >>= 1) mx = fmaxf(mx, __shfl_xor_sync(0xffffffffu, mx, o));
        float e = __expf(wv - mx);
        float sm = e;
#pragma unroll
        for (int o = 16; o; o >>= 1) sm += __shfl_xor_sync(0xffffffffu, sm, o);
        sw[t] = e * __frcp_rn(sm);
        int elem = cids[t] - 1;
        const int start4 = 1 + 8192 + 4096 + 2048;
        sp0[t] = __ldg(&pids[elem * 2])     - start4;
        sp1[t] = __ldg(&pids[elem * 2 + 1]) - start4;
    }
    __syncthreads();
    const uint2* s3 = (const uint2*)(g_bf + S3O);
    float a0 = 0.f, a1 = 0.f, a2 = 0.f, a3 = 0.f;
#pragma unroll
    for (int c = 0; c < 32; c++) {
        uint2 u0 = s3[(unsigned)sp0[c] * 256 + t];
        uint2 u1 = s3[(unsigned)sp1[c] * 256 + t];
        float wv = sw[c];
        a0 = fmaf(wv, lo_bf(u0.x) * lo_bf(u1.x), a0);
        a1 = fmaf(wv, hi_bf(u0.x) * hi_bf(u1.x), a1);
        a2 = fmaf(wv, lo_bf(u0.y) * lo_bf(u1.y), a2);
        a3 = fmaf(wv, hi_bf(u0.y) * hi_bf(u1.y), a3);
    }
    const float4* m2 = (const float4*)g_m;
    float4 b2 = m2[t];
    float4 o;
    o.x = logf(a0) + 4.f * logf(b2.x);
    o.y = logf(a1) + 4.f * logf(b2.y);
    o.z = logf(a2) + 4.f * logf(b2.z);
    o.w = logf(a3) + 4.f * logf(b2.w);
    ((float4*)out)[t] = o;
}

extern "C" void kernel_launch(void* const* d_in, const int* in_sizes, int n_in,
                              void* d_out, int out_size) {
    const int*   x      = (const int*)d_in[0];
    const float* logits = (const float*)d_in[1];
    const float* w1     = (const float*)d_in[2];
    const float* w2     = (const float*)d_in[3];
    const float* w3     = (const float*)d_in[4];
    const float* w4     = (const float*)d_in[5];
    const int*   pids1  = (const int*)d_in[6];
    const int*   pids2  = (const int*)d_in[7];
    const int*   pids3  = (const int*)d_in[8];
    const int*   pids4  = (const int*)d_in[9];
    const int*   cids1  = (const int*)d_in[10];
    const int*   cids2  = (const int*)d_in[11];
    const int*   cids3  = (const int*)d_in[12];
    const int*   cids4  = (const int*)d_in[13];

    k_inp<<<NV, 256>>>(logits, x);             // fused softmax+gather, zeros g_m

    // Layer 1: prod -> fp8 em1, fp8 gather sum -> bf16 s1.
    k_prod8<<<8192 / 4, 256>>>(pids1);
    k_sum8<<<4096, 128>>>(cids1, w1);

    // Layer 2: bf16 path (s1 ids start 8193). No renorm needed.
    k_prod<<<4096 / 4, 256>>>(EMO, S1O, pids2, 1 + 8192, 0);
    k_sum<<<2048, 128>>>(S2O, EMO, cids2, w2);
    k_max<<<dim3(4, 32), 256>>>(S2O, 2048 / 32);

    // Layer 3: prod from s2 (ids start 12289), renormalize by m2.
    k_prod<<<2048 / 4, 256>>>(EMO, S2O, pids3, 1 + 8192 + 4096, 1);
    k_sum<<<1024, 128>>>(S3O, EMO, cids3, w3);

    // Layer 4 (prod+sum) fused into the root kernel.
    k_root<<<1, 256>>>((float*)d_out, cids4, pids4, w4);
}

// round 15
// speedup vs baseline: 1.7845x; 1.1245x over previous
#include <cuda_runtime.h>
#include <cuda_bf16.h>
#include <cuda_fp16.h>

// ---------------------------------------------------------------------------
// TensorCircuit forward, linear domain, no renormalization.
//   input:  lin0[i,b] = softmax(in_logits[i])[x[b, i/32]]          (bf16)
//   prod1:  em1[e,b]  = lin0[p0,b]*lin0[p1,b] * 2^14               (fp8 e5m2)
//   sum1:   s1[s,b]   = 2^-14 * sum_c w~[s,c]*em1[cid,b]           (bf16, f16x2 acc)
//   prod2/3, sum2/3: bf16 gathers, fp32 accumulation. All values in (0,1];
//   worst-case em3 ~1e-32 is safely inside bf16 range (min normal 1.2e-38),
//   so no per-column renorm is needed anywhere.
//   root: acc = sum_c w4_c * (s3[p0_c]*2^60)*(s3[p1_c]*2^60)  (fp32-safe),
//         out = log(acc) - 120*ln2.
// ---------------------------------------------------------------------------

#define BATCH 1024
#define NV    256
#define NK    64
#define NM    32
#define NN0   8192

// bf16 arena (element offsets).
#define LIN0  0u
#define EMO   (8192u * 1024u)
#define S1O   (EMO + 8192u * 1024u)
#define S2O   (S1O + 4096u * 1024u)
#define S3O   (S2O + 2048u * 1024u)
#define BF_SZ (S3O + 1024u * 1024u)

__device__ __nv_bfloat16 g_bf[BF_SZ];
__device__ unsigned char g_e8[8192u * 1024u];   // em1, fp8 e5m2 (scaled 2^14)

#define EM1_SCALE    16384.0f
#define EM1_INVSCALE (1.0f / 16384.0f)
#define S3_SCALE     1.152921504606847e18f      // 2^60
#define LOG_S3SQ     83.17766166719344f         // 120 * ln(2)

// --- packing helpers ---------------------------------------------------------
__device__ __forceinline__ float lo_bf(unsigned u) { return __uint_as_float(u << 16); }
__device__ __forceinline__ float hi_bf(unsigned u) { return __uint_as_float(u & 0xffff0000u); }
__device__ __forceinline__ unsigned pack_bf2(float lo, float hi) {
    unsigned r;
    asm("cvt.rn.bf16x2.f32 %0, %1, %2;" : "=r"(r) : "f"(hi), "f"(lo));
    return r;
}
__device__ __forceinline__ unsigned short pack_e5(float lo, float hi) {
    unsigned short r;
    asm("cvt.rn.satfinite.e5m2x2.f32 %0, %1, %2;" : "=h"(r) : "f"(hi), "f"(lo));
    return r;
}
__device__ __forceinline__ __half2 unpack_e5(unsigned short v) {
    unsigned r;
    asm("cvt.rn.f16x2.e5m2x2 %0, %1;" : "=r"(r) : "h"(v));
    return *(__half2*)&r;
}

// Fused input layer: per-variable block computes the 32-row softmax tile in
// smem (transposed, padded), then each thread gathers for a COLUMN PAIR and
// writes packed bf16x2.
__global__ void __launch_bounds__(256) k_inp(const float* __restrict__ L,
                                             const int* __restrict__ x) {
    __shared__ float Pt[NK][NM + 1];
    int v = blockIdx.x;
    int warp = threadIdx.x >> 5, lane = threadIdx.x & 31;
#pragma unroll
    for (int i = 0; i < 4; i++) {
        int m = warp * 4 + i;
        const float* lr = L + (v * NM + m) * NK;
        float v0 = lr[lane], v1 = lr[lane + 32];
        float mx = fmaxf(v0, v1);
#pragma unroll
        for (int o = 16; o; o >>= 1) mx = fmaxf(mx, __shfl_xor_sync(0xffffffffu, mx, o));
        float e0 = __expf(v0 - mx), e1 = __expf(v1 - mx);
        float sm = e0 + e1;
#pragma unroll
        for (int o = 16; o; o >>= 1) sm += __shfl_xor_sync(0xffffffffu, sm, o);
        float inv = __frcp_rn(sm);
        Pt[lane][m]      = e0 * inv;
        Pt[lane + 32][m] = e1 * inv;
    }
    __syncthreads();
#pragma unroll
    for (int j = 0; j < 2; j++) {
        int b = (threadIdx.x + j * 256) * 2;
        int i0 = x[b * NV + v];
        int i1 = x[(b + 1) * NV + v];
        unsigned* o = (unsigned*)((unsigned short*)(g_bf + LIN0)
                                  + (unsigned)(v * NM) * BATCH + b);
#pragma unroll
        for (int m = 0; m < NM; m++)
            o[m * (BATCH / 2)] = pack_bf2(Pt[i0][m], Pt[i1][m]);
    }
}

// Layer-1 prod: em1[e,b] = lin0[p0,b]*lin0[p1,b] * 2^14, stored fp8 e5m2.
// 256 threads = 2 halves of 128; each half 2 elements (grid = E/4).
__global__ void __launch_bounds__(256) k_prod8(const int* __restrict__ pids) {
    int tid = threadIdx.x;
    int half = tid >> 7, t = tid & 127;
    unsigned e0 = blockIdx.x * 4 + half;          // elements e0, e0+2
    const int* pp = pids + e0 * 2;
    int p00 = __ldg(pp)     - 1;
    int p01 = __ldg(pp + 1) - 1;
    int p10 = __ldg(pp + 4) - 1;
    int p11 = __ldg(pp + 5) - 1;
    const uint4* prev = (const uint4*)(g_bf + LIN0);
    uint4 ua0 = prev[(unsigned)p00 * 128 + t];
    uint4 ub0 = prev[(unsigned)p01 * 128 + t];
    uint4 ua1 = prev[(unsigned)p10 * 128 + t];
    uint4 ub1 = prev[(unsigned)p11 * 128 + t];
    float r0[8], r1[8];
    r0[0] = lo_bf(ua0.x) * lo_bf(ub0.x);  r0[1] = hi_bf(ua0.x) * hi_bf(ub0.x);
    r0[2] = lo_bf(ua0.y) * lo_bf(ub0.y);  r0[3] = hi_bf(ua0.y) * hi_bf(ub0.y);
    r0[4] = lo_bf(ua0.z) * lo_bf(ub0.z);  r0[5] = hi_bf(ua0.z) * hi_bf(ub0.z);
    r0[6] = lo_bf(ua0.w) * lo_bf(ub0.w);  r0[7] = hi_bf(ua0.w) * hi_bf(ub0.w);
    r1[0] = lo_bf(ua1.x) * lo_bf(ub1.x);  r1[1] = hi_bf(ua1.x) * hi_bf(ub1.x);
    r1[2] = lo_bf(ua1.y) * lo_bf(ub1.y);  r1[3] = hi_bf(ua1.y) * hi_bf(ub1.y);
    r1[4] = lo_bf(ua1.z) * lo_bf(ub1.z);  r1[5] = hi_bf(ua1.z) * hi_bf(ub1.z);
    r1[6] = lo_bf(ua1.w) * lo_bf(ub1.w);  r1[7] = hi_bf(ua1.w) * hi_bf(ub1.w);
#pragma unroll
    for (int j = 0; j < 8; j++) { r0[j] *= EM1_SCALE; r1[j] *= EM1_SCALE; }
    uint2 o0, o1;
    o0.x = (unsigned)pack_e5(r0[0], r0[1]) | ((unsigned)pack_e5(r0[2], r0[3]) << 16);
    o0.y = (unsigned)pack_e5(r0[4], r0[5]) | ((unsigned)pack_e5(r0[6], r0[7]) << 16);
    o1.x = (unsigned)pack_e5(r1[0], r1[1]) | ((unsigned)pack_e5(r1[2], r1[3]) << 16);
    o1.y = (unsigned)pack_e5(r1[4], r1[5]) | ((unsigned)pack_e5(r1[6], r1[7]) << 16);
    uint2* out = (uint2*)g_e8;
    out[e0 * 128 + t]       = o0;
    out[(e0 + 2) * 128 + t] = o1;
}

// Layer-1 sum over fp8 em1: s1[s,b] = 2^-14 * sum_c w~[s,c]*em1[cid,b].
// One block per sum node; 128 threads x 8 fp8 columns; f16x2 accumulation.
__global__ void __launch_bounds__(128) k_sum8(const int* __restrict__ cids,
                                              const float* __restrict__ w) {
    __shared__ uint2 swc[32];     // .x = half2(w,w) bits, .y = row byte offset
    int s = blockIdx.x, t = threadIdx.x;
    if (t < 32) {
        float wv = w[s * 32 + t];
        float mx = wv;
#pragma unroll
        for (int o = 16; o; o >>= 1) mx = fmaxf(mx, __shfl_xor_sync(0xffffffffu, mx, o));
        float e = __expf(wv - mx);
        float sm = e;
#pragma unroll
        for (int o = 16; o; o >>= 1) sm += __shfl_xor_sync(0xffffffffu, sm, o);
        __half2 wh = __float2half2_rn(e * __frcp_rn(sm));
        swc[t] = make_uint2(*(unsigned*)&wh, (unsigned)(cids[s * 32 + t] - 1) * 1024u);
    }
    __syncthreads();
    const char* base = (const char*)g_e8 + t * 8;
    __half2 acc0 = __float2half2_rn(0.f), acc1 = acc0, acc2 = acc0, acc3 = acc0;
#pragma unroll
    for (int c = 0; c < 32; c++) {
        uint2 wc = swc[c];
        uint2 u = *(const uint2*)(base + wc.y);
        __half2 wh = *(__half2*)&wc.x;
        acc0 = __hfma2(wh, unpack_e5((unsigned short)(u.x & 0xffffu)), acc0);
        acc1 = __hfma2(wh, unpack_e5((unsigned short)(u.x >> 16)),     acc1);
        acc2 = __hfma2(wh, unpack_e5((unsigned short)(u.y & 0xffffu)), acc2);
        acc3 = __hfma2(wh, unpack_e5((unsigned short)(u.y >> 16)),     acc3);
    }
    float2 v0 = __half22float2(acc0), v1 = __half22float2(acc1);
    float2 v2 = __half22float2(acc2), v3 = __half22float2(acc3);
    uint4 o;
    o.x = pack_bf2(v0.x * EM1_INVSCALE, v0.y * EM1_INVSCALE);
    o.y = pack_bf2(v1.x * EM1_INVSCALE, v1.y * EM1_INVSCALE);
    o.z = pack_bf2(v2.x * EM1_INVSCALE, v2.y * EM1_INVSCALE);
    o.w = pack_bf2(v3.x * EM1_INVSCALE, v3.y * EM1_INVSCALE);
    ((uint4*)(g_bf + S1O))[s * 128 + t] = o;
}

// bf16 prod layer (layers 2-3): em[e,b] = prev[p0,b]*prev[p1,b].
// 256 threads = 2 halves of 128; each half 2 elements (grid = E/4).
__global__ void __launch_bounds__(256) k_prod(unsigned em_off, unsigned prev_off,
                                              const int* __restrict__ pids, int start) {
    int tid = threadIdx.x;
    int half = tid >> 7, t = tid & 127;
    unsigned e0 = blockIdx.x * 4 + half;
    const int* pp = pids + e0 * 2;
    int p00 = __ldg(pp)     - start;
    int p01 = __ldg(pp + 1) - start;
    int p10 = __ldg(pp + 4) - start;
    int p11 = __ldg(pp + 5) - start;
    const uint4* prev = (const uint4*)(g_bf + prev_off);
    uint4 ua0 = prev[(unsigned)p00 * 128 + t];
    uint4 ub0 = prev[(unsigned)p01 * 128 + t];
    uint4 ua1 = prev[(unsigned)p10 * 128 + t];
    uint4 ub1 = prev[(unsigned)p11 * 128 + t];
    float r0[8], r1[8];
    r0[0] = lo_bf(ua0.x) * lo_bf(ub0.x);  r0[1] = hi_bf(ua0.x) * hi_bf(ub0.x);
    r0[2] = lo_bf(ua0.y) * lo_bf(ub0.y);  r0[3] = hi_bf(ua0.y) * hi_bf(ub0.y);
    r0[4] = lo_bf(ua0.z) * lo_bf(ub0.z);  r0[5] = hi_bf(ua0.z) * hi_bf(ub0.z);
    r0[6] = lo_bf(ua0.w) * lo_bf(ub0.w);  r0[7] = hi_bf(ua0.w) * hi_bf(ub0.w);
    r1[0] = lo_bf(ua1.x) * lo_bf(ub1.x);  r1[1] = hi_bf(ua1.x) * hi_bf(ub1.x);
    r1[2] = lo_bf(ua1.y) * lo_bf(ub1.y);  r1[3] = hi_bf(ua1.y) * hi_bf(ub1.y);
    r1[4] = lo_bf(ua1.z) * lo_bf(ub1.z);  r1[5] = hi_bf(ua1.z) * hi_bf(ub1.z);
    r1[6] = lo_bf(ua1.w) * lo_bf(ub1.w);  r1[7] = hi_bf(ua1.w) * hi_bf(ub1.w);
    uint4* out = (uint4*)(g_bf + em_off);
    uint4 o0, o1;
    o0.x = pack_bf2(r0[0], r0[1]);  o0.y = pack_bf2(r0[2], r0[3]);
    o0.z = pack_bf2(r0[4], r0[5]);  o0.w = pack_bf2(r0[6], r0[7]);
    o1.x = pack_bf2(r1[0], r1[1]);  o1.y = pack_bf2(r1[2], r1[3]);
    o1.z = pack_bf2(r1[4], r1[5]);  o1.w = pack_bf2(r1[6], r1[7]);
    out[e0 * 128 + t]       = o0;
    out[(e0 + 2) * 128 + t] = o1;
}

// bf16 sum layer (layers 2-3): out[s,b] = sum_c w~[s,c]*em[cid,b]. fp32 acc.
__global__ void __launch_bounds__(128) k_sum(unsigned out_off, unsigned em_off,
                                             const int* __restrict__ cids,
                                             const float* __restrict__ w) {
    __shared__ uint2 swc[32];
    int s = blockIdx.x, t = threadIdx.x;
    if (t < 32) {
        float wv = w[s * 32 + t];
        float mx = wv;
#pragma unroll
        for (int o = 16; o; o >>= 1) mx = fmaxf(mx, __shfl_xor_sync(0xffffffffu, mx, o));
        float e = __expf(wv - mx);
        float sm = e;
#pragma unroll
        for (int o = 16; o; o >>= 1) sm += __shfl_xor_sync(0xffffffffu, sm, o);
        unsigned off = (unsigned)(cids[s * 32 + t] - 1) * 2048u;
        swc[t] = make_uint2(__float_as_uint(e * __frcp_rn(sm)), off);
    }
    __syncthreads();
    const char* base = (const char*)(g_bf + em_off) + t * 16;
    float a0 = 0.f, a1 = 0.f, a2 = 0.f, a3 = 0.f;
    float a4 = 0.f, a5 = 0.f, a6 = 0.f, a7 = 0.f;
#pragma unroll
    for (int c = 0; c < 32; c++) {
        uint2 wc = swc[c];
        uint4 u = *(const uint4*)(base + wc.y);
        float wv = __uint_as_float(wc.x);
        a0 = fmaf(wv, lo_bf(u.x), a0);  a1 = fmaf(wv, hi_bf(u.x), a1);
        a2 = fmaf(wv, lo_bf(u.y), a2);  a3 = fmaf(wv, hi_bf(u.y), a3);
        a4 = fmaf(wv, lo_bf(u.z), a4);  a5 = fmaf(wv, hi_bf(u.z), a5);
        a6 = fmaf(wv, lo_bf(u.w), a6);  a7 = fmaf(wv, hi_bf(u.w), a7);
    }
    uint4 o;
    o.x = pack_bf2(a0, a1);  o.y = pack_bf2(a2, a3);
    o.z = pack_bf2(a4, a5);  o.w = pack_bf2(a6, a7);
    ((uint4*)(g_bf + out_off))[s * 128 + t] = o;
}

// Root: fused layer-4 prod + root sum over the 32 referenced elements.
// s3 values scaled by 2^60 at load so fp32 pair-products cannot underflow;
// out = log(acc) - 120*ln2.
__global__ void __launch_bounds__(256) k_root(float* __restrict__ out,
                                              const int* __restrict__ cids,
                                              const int* __restrict__ pids,
                                              const float* __restrict__ w) {
    __shared__ float sw[32];
    __shared__ int   sp0[32], sp1[32];
    int t = threadIdx.x;
    if (t < 32) {
        float wv = w[t];
        float mx = wv;
#pragma unroll
        for (int o = 16; o; o >>= 1) mx = fmaxf(mx, __shfl_xor_sync(0xffffffffu, mx, o));
        float e = __expf(wv - mx);
        float sm = e;
#pragma unroll
        for (int o = 16; o; o >>= 1) sm += __shfl_xor_sync(0xffffffffu, sm, o);
        sw[t] = e * __frcp_rn(sm);
        int elem = cids[t] - 1;
        const int start4 = 1 + 8192 + 4096 + 2048;
        sp0[t] = __ldg(&pids[elem * 2])     - start4;
        sp1[t] = __ldg(&pids[elem * 2 + 1]) - start4;
    }
    __syncthreads();
    const uint2* s3 = (const uint2*)(g_bf + S3O);
    float a0 = 0.f, a1 = 0.f, a2 = 0.f, a3 = 0.f;
#pragma unroll
    for (int c = 0; c < 32; c++) {
        uint2 u0 = s3[(unsigned)sp0[c] * 256 + t];
        uint2 u1 = s3[(unsigned)sp1[c] * 256 + t];
        float wv = sw[c];
        a0 = fmaf(wv, (lo_bf(u0.x) * S3_SCALE) * (lo_bf(u1.x) * S3_SCALE), a0);
        a1 = fmaf(wv, (hi_bf(u0.x) * S3_SCALE) * (hi_bf(u1.x) * S3_SCALE), a1);
        a2 = fmaf(wv, (lo_bf(u0.y) * S3_SCALE) * (lo_bf(u1.y) * S3_SCALE), a2);
        a3 = fmaf(wv, (hi_bf(u0.y) * S3_SCALE) * (hi_bf(u1.y) * S3_SCALE), a3);
    }
    float4 o;
    o.x = logf(a0) - LOG_S3SQ;
    o.y = logf(a1) - LOG_S3SQ;
    o.z = logf(a2) - LOG_S3SQ;
    o.w = logf(a3) - LOG_S3SQ;
    ((float4*)out)[t] = o;
}

extern "C" void kernel_launch(void* const* d_in, const int* in_sizes, int n_in,
                              void* d_out, int out_size) {
    const int*   x      = (const int*)d_in[0];
    const float* logits = (const float*)d_in[1];
    const float* w1     = (const float*)d_in[2];
    const float* w2     = (const float*)d_in[3];
    const float* w3     = (const float*)d_in[4];
    const float* w4     = (const float*)d_in[5];
    const int*   pids1  = (const int*)d_in[6];
    const int*   pids2  = (const int*)d_in[7];
    const int*   pids3  = (const int*)d_in[8];
    const int*   pids4  = (const int*)d_in[9];
    const int*   cids1  = (const int*)d_in[10];
    const int*   cids2  = (const int*)d_in[11];
    const int*   cids3  = (const int*)d_in[12];
    const int*   cids4  = (const int*)d_in[13];

    k_inp<<<NV, 256>>>(logits, x);             // fused softmax+gather

    // Layer 1: prod -> fp8 em1, fp8 gather sum -> bf16 s1.
    k_prod8<<<8192 / 4, 256>>>(pids1);
    k_sum8<<<4096, 128>>>(cids1, w1);

    // Layer 2 (s1 ids start 8193).
    k_prod<<<4096 / 4, 256>>>(EMO, S1O, pids2, 1 + 8192);
    k_sum<<<2048, 128>>>(S2O, EMO, cids2, w2);

    // Layer 3 (s2 ids start 12289). No renorm anywhere.
    k_prod<<<2048 / 4, 256>>>(EMO, S2O, pids3, 1 + 8192 + 4096);
    k_sum<<<1024, 128>>>(S3O, EMO, cids3, w3);

    // Layer 4 (prod+sum) fused into the root kernel, with 2^60 scaling.
    k_root<<<1, 256>>>((float*)d_out, cids4, pids4, w4);
}